// round 15
// baseline (speedup 1.0000x reference)
#include <cuda_runtime.h>
#include <cstdint>
#include <math.h>

#define MAXN 50000
#define MAXE 800000
#define DIM  128

typedef unsigned long long ull;
#define FULLMASK 0xffffffffu

// ---- scratch (static __device__ arrays; no allocation allowed) ----
// counts/cursor are zero at module load; the zero_kernel on the side stream
// restores them each call (ordered before the join), so every invocation and
// every graph replay starts from zeros.
__device__ float  g_q   [MAXN * DIM];
__device__ float  g_k   [MAXN * DIM];
__device__ float  g_v   [MAXN * DIM];
__device__ float  g_skip[MAXN * DIM];
__device__ float  g_qwe [MAXN * 2 * DIM];   // [N][h*128+d]
__device__ float  g_z   [MAXN * 2 * DIM];   // [N][h*128+d]
__device__ float  g_vagg[MAXN * DIM];
__device__ float  g_pre [MAXN * DIM];
__device__ float  g_Wqe [2 * DIM * DIM];    // [h][k][d]
__device__ float  g_bqe [2 * DIM];          // [h][d]
__device__ int    g_counts [MAXN];
__device__ int    g_cursor [MAXN];
__device__ int    g_offsets[MAXN + 1];
__device__ int    g_perm   [MAXE];

// ------------------------------------------------------------------
__device__ __forceinline__ void ffma2(ull &d, ull a, ull b) {
    asm("fma.rn.f32x2 %0, %1, %2, %0;" : "+l"(d) : "l"(a), "l"(b));
}
__device__ __forceinline__ float lo32(ull v) { union { ull u; float2 f; } c; c.u = v; return c.f.x; }
__device__ __forceinline__ float hi32(ull v) { union { ull u; float2 f; } c; c.u = v; return c.f.y; }

// ------------------------------------------------------------------
__global__ void zero_kernel(int* a, int* b, int n) {
    int i = blockIdx.x * blockDim.x + threadIdx.x;
    if (i < n) { a[i] = 0; b[i] = 0; }
}

__global__ void count_kernel(const int* __restrict__ dst, int* __restrict__ counts, int e) {
    int i = blockIdx.x * blockDim.x + threadIdx.x;
    if (i < e) atomicAdd(&counts[dst[i]], 1);
}

// Wqe[h][k][d] = sum_c Wq[k][h*64+c] * We[d][h*64+c] ; bqe likewise
__global__ void wqe_prep(const float* __restrict__ Wq, const float* __restrict__ bq,
                         const float* __restrict__ We,
                         float* __restrict__ Wqe, float* __restrict__ bqe) {
    __shared__ float wq_s[16][64];
    const int h  = blockIdx.x >> 3;
    const int kt = (blockIdx.x & 7) * 16;
    const int d  = threadIdx.x;

    for (int idx = d; idx < 16 * 64; idx += 128) {
        int kk = idx >> 6, c = idx & 63;
        wq_s[kk][c] = Wq[(size_t)(kt + kk) * DIM + h * 64 + c];
    }
    __syncthreads();

    float wer[64];
#pragma unroll
    for (int c4 = 0; c4 < 64; c4 += 4) {
        float4 w = *(const float4*)&We[(size_t)d * DIM + h * 64 + c4];
        wer[c4 + 0] = w.x; wer[c4 + 1] = w.y; wer[c4 + 2] = w.z; wer[c4 + 3] = w.w;
    }
#pragma unroll 4
    for (int kk = 0; kk < 16; kk++) {
        float acc = 0.f;
#pragma unroll
        for (int c = 0; c < 64; c++) acc += wq_s[kk][c] * wer[c];
        Wqe[(size_t)h * DIM * DIM + (size_t)(kt + kk) * DIM + d] = acc;
    }
    if (kt == 0) {
        float acc = 0.f;
#pragma unroll
        for (int c = 0; c < 64; c++) acc += bq[h * 64 + c] * wer[c];
        bqe[h * DIM + d] = acc;
    }
}

// single-block scan over n counts -> exclusive offsets, offsets[n] = total
__global__ void scan_kernel(const int* __restrict__ counts, int* __restrict__ offsets, int n) {
    __shared__ int part[1024];
    int tid = threadIdx.x;
    int ch = (n + 1023) >> 10;
    int b = tid * ch;
    int eidx = b + ch; if (eidx > n) eidx = n;
    int s = 0;
    for (int i = b; i < eidx; i++) s += counts[i];
    part[tid] = s;
    __syncthreads();
    for (int off = 1; off < 1024; off <<= 1) {
        int v = (tid >= off) ? part[tid - off] : 0;
        __syncthreads();
        part[tid] += v;
        __syncthreads();
    }
    int excl = (tid == 0) ? 0 : part[tid - 1];
    for (int i = b; i < eidx; i++) { offsets[i] = excl; excl += counts[i]; }
    if (tid == 1023) offsets[n] = part[1023];
}

__global__ void scatter_kernel(const int* __restrict__ dst, const int* __restrict__ offsets,
                               int* __restrict__ cursor, int* __restrict__ perm, int e) {
    int i = blockIdx.x * blockDim.x + threadIdx.x;
    if (i < e) {
        int d = dst[i];
        int pos = offsets[d] + atomicAdd(&cursor[d], 1);
        perm[pos] = i;
    }
}

// ------------------------------------------------------------------
// Fused x-GEMM (round-14 winner, unchanged).
struct Slice { const float* B; const float* bias; float* C; int ldC; int cOff; };
struct Slices6 { Slice s[6]; };

#define GSTR 10   // padded group stride in float2 (8 data + 2 pad)

__global__ __launch_bounds__(128, 3)
void gemm_multi(const float* __restrict__ A, int M, Slices6 sl) {
    constexpr int N = 128, CPT = 8, ROWG = 8, RPT = 8, PAIRS = 4;
    constexpr int KC = 16, STR = 12;
    constexpr int XSW = (64 / RPT) * STR;      // 96
    constexpr int WSW = (N / 8) * GSTR;        // 160 float2 per k row

    __shared__ float  xs [2][KC][XSW];
    __shared__ float2 ws2[2][KC][WSW];

    const Slice s = sl.s[blockIdx.y];
    const int tid = threadIdx.x;
    const int y = tid % ROWG;
    const int x = tid / ROWG;
    const int n0 = blockIdx.x * 64;
    const int abase = y * STR;
    const int wbase = x * GSTR;

    ull acc[PAIRS][CPT];
#pragma unroll
    for (int p = 0; p < PAIRS; p++)
#pragma unroll
        for (int c = 0; c < CPT; c++) acc[p][c] = 0ull;

    auto stage = [&](int bb, int kc) {
        int rr = tid >> 1;
        int kh = (tid & 1) * 8;
        int row = n0 + rr;
        float4 a0 = make_float4(0.f, 0.f, 0.f, 0.f), a1 = a0;
        if (row < M) {
            const float* ap = &A[(size_t)row * DIM + kc + kh];
            a0 = *(const float4*)ap;
            a1 = *(const float4*)(ap + 4);
        }
        int pp = (rr / RPT) * STR + (rr % RPT);
        xs[bb][kh + 0][pp] = a0.x; xs[bb][kh + 1][pp] = a0.y;
        xs[bb][kh + 2][pp] = a0.z; xs[bb][kh + 3][pp] = a0.w;
        xs[bb][kh + 4][pp] = a1.x; xs[bb][kh + 5][pp] = a1.y;
        xs[bb][kh + 6][pp] = a1.z; xs[bb][kh + 7][pp] = a1.w;
#pragma unroll
        for (int it = 0; it < KC * N / (128 * 4); it++) {
            int idx = tid + it * 128;
            int kk = idx / (N / 4);
            int j  = (idx * 4) % N;
            int jp = (j >> 3) * GSTR + (j & 7);
            float4 w = *(const float4*)&s.B[(size_t)(kc + kk) * DIM + j];
            ws2[bb][kk][jp + 0] = make_float2(w.x, w.x);
            ws2[bb][kk][jp + 1] = make_float2(w.y, w.y);
            ws2[bb][kk][jp + 2] = make_float2(w.z, w.z);
            ws2[bb][kk][jp + 3] = make_float2(w.w, w.w);
        }
    };

    stage(0, 0);
    __syncthreads();
    const int nIt = DIM / KC;
    for (int ch = 0; ch < nIt; ch++) {
        int cur = ch & 1;
        if (ch + 1 < nIt) stage(cur ^ 1, (ch + 1) * KC);
#pragma unroll
        for (int k = 0; k < KC; k++) {
            ulonglong2 a0 = *(const ulonglong2*)&xs[cur][k][abase];
            ulonglong2 a1 = *(const ulonglong2*)&xs[cur][k][abase + 4];
            ull ap[PAIRS] = { a0.x, a0.y, a1.x, a1.y };
            ulonglong2 wq0 = *(const ulonglong2*)&ws2[cur][k][wbase + 0];
            ulonglong2 wq1 = *(const ulonglong2*)&ws2[cur][k][wbase + 2];
            ulonglong2 wq2 = *(const ulonglong2*)&ws2[cur][k][wbase + 4];
            ulonglong2 wq3 = *(const ulonglong2*)&ws2[cur][k][wbase + 6];
            ull wd[CPT] = { wq0.x, wq0.y, wq1.x, wq1.y, wq2.x, wq2.y, wq3.x, wq3.y };
#pragma unroll
            for (int p = 0; p < PAIRS; p++)
#pragma unroll
                for (int c = 0; c < CPT; c++)
                    ffma2(acc[p][c], ap[p], wd[c]);
        }
        __syncthreads();
    }

    float bj[CPT];
#pragma unroll
    for (int c = 0; c < CPT; c++) bj[c] = s.bias[s.cOff + CPT * x + c];
#pragma unroll
    for (int p = 0; p < PAIRS; p++) {
#pragma unroll
        for (int half = 0; half < 2; half++) {
            int row = n0 + RPT * y + 2 * p + half;
            if (row >= M) continue;
            float* cp = &s.C[(size_t)row * s.ldC + s.cOff + CPT * x];
            float4 o0, o1;
            if (half == 0) {
                o0 = make_float4(lo32(acc[p][0]) + bj[0], lo32(acc[p][1]) + bj[1],
                                 lo32(acc[p][2]) + bj[2], lo32(acc[p][3]) + bj[3]);
                o1 = make_float4(lo32(acc[p][4]) + bj[4], lo32(acc[p][5]) + bj[5],
                                 lo32(acc[p][6]) + bj[6], lo32(acc[p][7]) + bj[7]);
            } else {
                o0 = make_float4(hi32(acc[p][0]) + bj[0], hi32(acc[p][1]) + bj[1],
                                 hi32(acc[p][2]) + bj[2], hi32(acc[p][3]) + bj[3]);
                o1 = make_float4(hi32(acc[p][4]) + bj[4], hi32(acc[p][5]) + bj[5],
                                 hi32(acc[p][6]) + bj[6], hi32(acc[p][7]) + bj[7]);
            }
            *(float4*)cp       = o0;
            *(float4*)(cp + 4) = o1;
        }
    }
}

// ------------------------------------------------------------------
// Generic double-buffered FFMA2 GEMM (pre x2 and proj), unchanged.
template<int N>
__global__ __launch_bounds__(128, 3)
void gemm_p(const float* __restrict__ A, int ldA, int aOff,
            const float* __restrict__ B, int ldB,
            int K,
            const float* __restrict__ bias,
            const float* __restrict__ add0, const float* __restrict__ add1, int ldAdd,
            float* __restrict__ C, int ldC, int cOff, int M) {
    constexpr int CPT   = 8;
    constexpr int COLG  = N / CPT;
    constexpr int ROWG  = 128 / COLG;
    constexpr int RPT   = 64 / ROWG;
    constexpr int PAIRS = RPT / 2;
    constexpr int KC    = 16;
    constexpr int STR   = 12;
    constexpr int XSW   = (64 / RPT) * STR;
    constexpr int WSW   = (N / 8) * GSTR;

    __shared__ float  xs [2][KC][XSW];
    __shared__ float2 ws2[2][KC][WSW];

    const int tid = threadIdx.x;
    const int y = tid % ROWG;
    const int x = tid / ROWG;
    const int n0 = blockIdx.x * 64;
    const int abase = y * STR;
    const int wbase = x * GSTR;

    ull acc[PAIRS][CPT];
#pragma unroll
    for (int p = 0; p < PAIRS; p++)
#pragma unroll
        for (int c = 0; c < CPT; c++) acc[p][c] = 0ull;

    auto stage = [&](int bb, int kc) {
        int rr = tid >> 1;
        int kh = (tid & 1) * 8;
        int row = n0 + rr;
        float4 a0 = make_float4(0.f, 0.f, 0.f, 0.f), a1 = a0;
        if (row < M) {
            const float* ap = &A[(size_t)row * ldA + aOff + kc + kh];
            a0 = *(const float4*)ap;
            a1 = *(const float4*)(ap + 4);
        }
        int pp = (rr / RPT) * STR + (rr % RPT);
        xs[bb][kh + 0][pp] = a0.x; xs[bb][kh + 1][pp] = a0.y;
        xs[bb][kh + 2][pp] = a0.z; xs[bb][kh + 3][pp] = a0.w;
        xs[bb][kh + 4][pp] = a1.x; xs[bb][kh + 5][pp] = a1.y;
        xs[bb][kh + 6][pp] = a1.z; xs[bb][kh + 7][pp] = a1.w;
#pragma unroll
        for (int it = 0; it < KC * N / (128 * 4); it++) {
            int idx = tid + it * 128;
            int kk = idx / (N / 4);
            int j  = (idx * 4) % N;
            int jp = (j >> 3) * GSTR + (j & 7);
            float4 w = *(const float4*)&B[(size_t)(kc + kk) * ldB + j];
            ws2[bb][kk][jp + 0] = make_float2(w.x, w.x);
            ws2[bb][kk][jp + 1] = make_float2(w.y, w.y);
            ws2[bb][kk][jp + 2] = make_float2(w.z, w.z);
            ws2[bb][kk][jp + 3] = make_float2(w.w, w.w);
        }
    };

    stage(0, 0);
    __syncthreads();
    const int nIt = K / KC;
    for (int ch = 0; ch < nIt; ch++) {
        int cur = ch & 1;
        if (ch + 1 < nIt) stage(cur ^ 1, (ch + 1) * KC);
#pragma unroll
        for (int k = 0; k < KC; k++) {
            ull ap[PAIRS];
            if (PAIRS == 4) {
                ulonglong2 a0 = *(const ulonglong2*)&xs[cur][k][abase];
                ulonglong2 a1 = *(const ulonglong2*)&xs[cur][k][abase + 4];
                ap[0] = a0.x; ap[1] = a0.y;
                ap[PAIRS - 2] = a1.x; ap[PAIRS - 1] = a1.y;
            } else {
                ulonglong2 a0 = *(const ulonglong2*)&xs[cur][k][abase];
                ap[0] = a0.x; ap[PAIRS - 1] = a0.y;
            }
            ulonglong2 wq0 = *(const ulonglong2*)&ws2[cur][k][wbase + 0];
            ulonglong2 wq1 = *(const ulonglong2*)&ws2[cur][k][wbase + 2];
            ulonglong2 wq2 = *(const ulonglong2*)&ws2[cur][k][wbase + 4];
            ulonglong2 wq3 = *(const ulonglong2*)&ws2[cur][k][wbase + 6];
            ull wd[CPT] = { wq0.x, wq0.y, wq1.x, wq1.y, wq2.x, wq2.y, wq3.x, wq3.y };
#pragma unroll
            for (int p = 0; p < PAIRS; p++)
#pragma unroll
                for (int c = 0; c < CPT; c++)
                    ffma2(acc[p][c], ap[p], wd[c]);
        }
        __syncthreads();
    }

    float bj[CPT];
#pragma unroll
    for (int c = 0; c < CPT; c++) bj[c] = bias ? bias[cOff + CPT * x + c] : 0.f;
#pragma unroll
    for (int p = 0; p < PAIRS; p++) {
#pragma unroll
        for (int half = 0; half < 2; half++) {
            int row = n0 + RPT * y + 2 * p + half;
            if (row >= M) continue;
            float o[CPT];
#pragma unroll
            for (int c = 0; c < CPT; c++)
                o[c] = (half ? hi32(acc[p][c]) : lo32(acc[p][c])) + bj[c];
            size_t abidx = (size_t)row * ldAdd + cOff + CPT * x;
            if (add0) {
                float4 a = *(const float4*)&add0[abidx];
                float4 b = *(const float4*)&add0[abidx + 4];
                o[0] += a.x; o[1] += a.y; o[2] += a.z; o[3] += a.w;
                o[4] += b.x; o[5] += b.y; o[6] += b.z; o[7] += b.w;
            }
            if (add1) {
                float4 a = *(const float4*)&add1[abidx];
                float4 b = *(const float4*)&add1[abidx + 4];
                o[0] += a.x; o[1] += a.y; o[2] += a.z; o[3] += a.w;
                o[4] += b.x; o[5] += b.y; o[6] += b.z; o[7] += b.w;
            }
            float* cp = &C[(size_t)row * ldC + cOff + CPT * x];
            *(float4*)cp       = make_float4(o[0], o[1], o[2], o[3]);
            *(float4*)(cp + 4) = make_float4(o[4], o[5], o[6], o[7]);
        }
    }
}

// ------------------------------------------------------------------
// Attention v2: 16 lanes per edge, 2 edges per warp.
// Each lane owns 8 columns (2 float4). Reduction is 4 shfl levels within the
// 16-lane group; one SHFL/MUFU instruction serves two edges. Invalid (tail)
// edges masked via e=0 so denominators stay exact. Subgroup partials merged
// once per node via shfl_xor(...,16).
__global__ void attn_kernel(const int* __restrict__ src_arr, const int* __restrict__ offsets,
                            const int* __restrict__ perm,
                            const float* __restrict__ q, const float* __restrict__ k,
                            const float* __restrict__ v, const float* __restrict__ qwe,
                            const float* __restrict__ edge_attr,
                            float* __restrict__ z, float* __restrict__ vagg, int n) {
    int warp = (blockIdx.x * blockDim.x + threadIdx.x) >> 5;
    int lane = threadIdx.x & 31;
    if (warp >= n) return;
    const int i = warp;
    const int beg = offsets[i], end = offsets[i + 1];
    const int g   = lane >> 4;      // edge subgroup (0/1)
    const int l16 = lane & 15;      // lane within subgroup
    const int head8 = l16 >> 3;     // this lane's columns belong to head 0/1

    const float4* qr  = (const float4*)&q  [(size_t)i * 128 + l16 * 8];
    const float4* w0r = (const float4*)&qwe[(size_t)i * 256 + l16 * 8];
    const float4* w1r = (const float4*)&qwe[(size_t)i * 256 + 128 + l16 * 8];
    float4 qa = qr[0],  qb = qr[1];
    float4 w0a = w0r[0], w0b = w0r[1];
    float4 w1a = w1r[0], w1b = w1r[1];

    float l0 = 0.f, l1 = 0.f;
    float4 zf = make_float4(0.f, 0.f, 0.f, 0.f);
    float4 az0a = zf, az0b = zf, az1a = zf, az1b = zf, ava = zf, avb = zf;

    for (int c = beg; c < end; c += 32) {
        int t = c + lane;
        int epre = 0, spre = 0;
        if (t < end) { epre = perm[t]; spre = src_arr[epre]; }
        int cnt = end - c; if (cnt > 32) cnt = 32;
        int nIt = (cnt + 1) >> 1;

        // prefetch edge pair 0 (indices g, unconditionally safe: defaults to row 0)
        int ej = __shfl_sync(FULLMASK, epre, g);
        int sj = __shfl_sync(FULLMASK, spre, g);
        const float4* eap = (const float4*)&edge_attr[(size_t)ej * 128 + l16 * 8];
        const float4* kp  = (const float4*)&k[(size_t)sj * 128 + l16 * 8];
        const float4* vp  = (const float4*)&v[(size_t)sj * 128 + l16 * 8];
        float4 eaa = __ldcs(eap), eab = __ldcs(eap + 1);
        float4 ka  = kp[0], kb = kp[1];
        float4 va  = vp[0], vb = vp[1];

        for (int j = 0; j < nIt; j++) {
            float4 eaan = eaa, eabn = eab, kan = ka, kbn = kb, van = va, vbn = vb;
            if (j + 1 < nIt) {
                int idx1 = 2 * (j + 1) + g;
                int ej1 = __shfl_sync(FULLMASK, epre, idx1 & 31);
                int sj1 = __shfl_sync(FULLMASK, spre, idx1 & 31);
                const float4* eap1 = (const float4*)&edge_attr[(size_t)ej1 * 128 + l16 * 8];
                const float4* kp1  = (const float4*)&k[(size_t)sj1 * 128 + l16 * 8];
                const float4* vp1  = (const float4*)&v[(size_t)sj1 * 128 + l16 * 8];
                eaan = __ldcs(eap1); eabn = __ldcs(eap1 + 1);
                kan = kp1[0]; kbn = kp1[1];
                van = vp1[0]; vbn = vp1[1];
            }

            float pqk = qa.x * ka.x + qa.y * ka.y + qa.z * ka.z + qa.w * ka.w
                      + qb.x * kb.x + qb.y * kb.y + qb.z * kb.z + qb.w * kb.w;
            float p0  = eaa.x * w0a.x + eaa.y * w0a.y + eaa.z * w0a.z + eaa.w * w0a.w
                      + eab.x * w0b.x + eab.y * w0b.y + eab.z * w0b.z + eab.w * w0b.w;
            float p1  = eaa.x * w1a.x + eaa.y * w1a.y + eaa.z * w1a.z + eaa.w * w1a.w
                      + eab.x * w1b.x + eab.y * w1b.y + eab.z * w1b.z + eab.w * w1b.w;
            float s0 = p0 + (head8 ? 0.f : pqk);
            float s1 = p1 + (head8 ? pqk : 0.f);

            // 4-level butterfly within the 16-lane subgroup (offsets < 16)
#pragma unroll
            for (int off = 8; off; off >>= 1) {
                s0 += __shfl_xor_sync(FULLMASK, s0, off);
                s1 += __shfl_xor_sync(FULLMASK, s1, off);
            }

            bool valid = (2 * j + g) < cnt;
            float e0 = valid ? __expf(fminf(s0 * 0.125f, 80.f)) : 0.f;
            float e1 = valid ? __expf(fminf(s1 * 0.125f, 80.f)) : 0.f;
            l0 += e0; l1 += e1;
            az0a.x += e0 * eaa.x; az0a.y += e0 * eaa.y; az0a.z += e0 * eaa.z; az0a.w += e0 * eaa.w;
            az0b.x += e0 * eab.x; az0b.y += e0 * eab.y; az0b.z += e0 * eab.z; az0b.w += e0 * eab.w;
            az1a.x += e1 * eaa.x; az1a.y += e1 * eaa.y; az1a.z += e1 * eaa.z; az1a.w += e1 * eaa.w;
            az1b.x += e1 * eab.x; az1b.y += e1 * eab.y; az1b.z += e1 * eab.z; az1b.w += e1 * eab.w;
            float eh = head8 ? e1 : e0;
            ava.x += eh * va.x; ava.y += eh * va.y; ava.z += eh * va.z; ava.w += eh * va.w;
            avb.x += eh * vb.x; avb.y += eh * vb.y; avb.z += eh * vb.z; avb.w += eh * vb.w;

            eaa = eaan; eab = eabn; ka = kan; kb = kbn; va = van; vb = vbn;
        }
    }

    // merge the two subgroups (each processed different edges of node i)
    l0 += __shfl_xor_sync(FULLMASK, l0, 16);
    l1 += __shfl_xor_sync(FULLMASK, l1, 16);
#define MRG(f) f += __shfl_xor_sync(FULLMASK, f, 16)
    MRG(az0a.x); MRG(az0a.y); MRG(az0a.z); MRG(az0a.w);
    MRG(az0b.x); MRG(az0b.y); MRG(az0b.z); MRG(az0b.w);
    MRG(az1a.x); MRG(az1a.y); MRG(az1a.z); MRG(az1a.w);
    MRG(az1b.x); MRG(az1b.y); MRG(az1b.z); MRG(az1b.w);
    MRG(ava.x);  MRG(ava.y);  MRG(ava.z);  MRG(ava.w);
    MRG(avb.x);  MRG(avb.y);  MRG(avb.z);  MRG(avb.w);
#undef MRG

    float il0 = (end > beg) ? 1.f / l0 : 0.f;
    float il1 = (end > beg) ? 1.f / l1 : 0.f;

    if (g == 0) {
        float4* zp = (float4*)&z[(size_t)i * 256 + l16 * 8];
        zp[0] = make_float4(az0a.x * il0, az0a.y * il0, az0a.z * il0, az0a.w * il0);
        zp[1] = make_float4(az0b.x * il0, az0b.y * il0, az0b.z * il0, az0b.w * il0);
        float ilh = head8 ? il1 : il0;
        float4* vg = (float4*)&vagg[(size_t)i * 128 + l16 * 8];
        vg[0] = make_float4(ava.x * ilh, ava.y * ilh, ava.z * ilh, ava.w * ilh);
        vg[1] = make_float4(avb.x * ilh, avb.y * ilh, avb.z * ilh, avb.w * ilh);
    } else {
        float4* zp = (float4*)&z[(size_t)i * 256 + 128 + l16 * 8];
        zp[0] = make_float4(az1a.x * il1, az1a.y * il1, az1a.z * il1, az1a.w * il1);
        zp[1] = make_float4(az1b.x * il1, az1b.y * il1, az1b.z * il1, az1b.w * il1);
    }
}

// ------------------------------------------------------------------
extern "C" void kernel_launch(void* const* d_in, const int* in_sizes, int n_in,
                              void* d_out, int out_size) {
    const float* x     = (const float*)d_in[0];
    const float* eattr = (const float*)d_in[1];
    const float* Wq    = (const float*)d_in[2];
    const float* bq    = (const float*)d_in[3];
    const float* Wk    = (const float*)d_in[4];
    const float* bk    = (const float*)d_in[5];
    const float* Wv    = (const float*)d_in[6];
    const float* bv    = (const float*)d_in[7];
    const float* We    = (const float*)d_in[8];
    const float* Wskip = (const float*)d_in[9];
    const float* bskip = (const float*)d_in[10];
    const float* Wproj = (const float*)d_in[11];
    const float* bproj = (const float*)d_in[12];
    const int*   ei    = (const int*)d_in[13];

    const int n = in_sizes[0] / DIM;       // 50000
    const int e = in_sizes[1] / DIM;       // 800000
    const int* src = ei;                   // edge_index[0]
    const int* dst = ei + e;               // edge_index[1]

    float *pq, *pk, *pv, *pskip, *pqwe, *pz, *pvagg, *ppre, *pWqe, *pbqe;
    int *pcnt, *pcur, *poff, *pperm;
    cudaGetSymbolAddress((void**)&pq,    g_q);
    cudaGetSymbolAddress((void**)&pk,    g_k);
    cudaGetSymbolAddress((void**)&pv,    g_v);
    cudaGetSymbolAddress((void**)&pskip, g_skip);
    cudaGetSymbolAddress((void**)&pqwe,  g_qwe);
    cudaGetSymbolAddress((void**)&pz,    g_z);
    cudaGetSymbolAddress((void**)&pvagg, g_vagg);
    cudaGetSymbolAddress((void**)&ppre,  g_pre);
    cudaGetSymbolAddress((void**)&pWqe,  g_Wqe);
    cudaGetSymbolAddress((void**)&pbqe,  g_bqe);
    cudaGetSymbolAddress((void**)&pcnt,  g_counts);
    cudaGetSymbolAddress((void**)&pcur,  g_cursor);
    cudaGetSymbolAddress((void**)&poff,  g_offsets);
    cudaGetSymbolAddress((void**)&pperm, g_perm);

    const int gb = (n + 63) / 64;          // 64-row GEMM blocks (782)
    const int wb = (n * 32 + 255) / 256;   // warp-per-node grid
    const int cb = (e + 255) / 256;        // edge-parallel blocks

    // ---- side stream for CSR build + skip GEMM (joined via events) ----
    cudaStream_t s2;
    cudaStreamCreateWithFlags(&s2, cudaStreamNonBlocking);
    cudaEvent_t evFork, evCsr, evSkip;
    cudaEventCreateWithFlags(&evFork, cudaEventDisableTiming);
    cudaEventCreateWithFlags(&evCsr,  cudaEventDisableTiming);
    cudaEventCreateWithFlags(&evSkip, cudaEventDisableTiming);

    // fork
    cudaEventRecord(evFork, 0);
    cudaStreamWaitEvent(s2, evFork, 0);

    // main: Wqe precompute (needed by gemm_multi slices 4,5)
    wqe_prep<<<16, 128>>>(Wq, bq, We, pWqe, pbqe);

    // s2: CSR chain (counts/cursor are zero on entry; re-zeroed below)
    count_kernel<<<cb, 256, 0, s2>>>(dst, pcnt, e);
    scan_kernel<<<1, 1024, 0, s2>>>(pcnt, poff, n);

    // main: 5-slice fused x-GEMM (q, k, v, qwe0, qwe1) -- overlaps CSR chain
    Slices6 sl;
    sl.s[0] = { Wq,              bq,    pq,    DIM, 0   };
    sl.s[1] = { Wk,              bk,    pk,    DIM, 0   };
    sl.s[2] = { Wv,              bv,    pv,    DIM, 0   };
    sl.s[3] = { pWqe,            pbqe,  pqwe,  256, 0   };
    sl.s[4] = { pWqe + DIM*DIM,  pbqe,  pqwe,  256, 128 };
    gemm_multi<<<dim3(gb, 5), 128>>>(x, n, sl);

    // s2: finish CSR, restore counts/cursor for next replay, then skip GEMM
    scatter_kernel<<<cb, 256, 0, s2>>>(dst, poff, pcur, pperm, e);
    zero_kernel<<<(n + 255) / 256, 256, 0, s2>>>(pcnt, pcur, n);
    cudaEventRecord(evCsr, s2);
    Slices6 sk;
    sk.s[0] = { Wskip, bskip, pskip, DIM, 0 };
    gemm_multi<<<dim3(gb, 1), 128, 0, s2>>>(x, n, sk);   // overlaps attn
    cudaEventRecord(evSkip, s2);

    // main: attention needs q/k/v/qwe (main) + CSR (evCsr)
    cudaStreamWaitEvent(0, evCsr, 0);
    attn_kernel<<<wb, 256>>>(src, poff, pperm, pq, pk, pv, pqwe, eattr, pz, pvagg, n);

    // main: pre needs vagg/z (attn) + skip (evSkip)
    cudaStreamWaitEvent(0, evSkip, 0);
    gemm_p<64><<<gb, 128>>>(pz, 256, 0,   We,      DIM, DIM, nullptr, pvagg, pskip, DIM, ppre, DIM, 0,  n);
    gemm_p<64><<<gb, 128>>>(pz, 256, 128, We + 64, DIM, DIM, nullptr, pvagg, pskip, DIM, ppre, DIM, 64, n);

    // main: out = pre @ Wproj + bproj
    gemm_p<128><<<gb, 128>>>(ppre, DIM, 0, Wproj, DIM, DIM, bproj, nullptr, nullptr, 0, (float*)d_out, DIM, 0, n);

    cudaEventDestroy(evFork);
    cudaEventDestroy(evCsr);
    cudaEventDestroy(evSkip);
    cudaStreamDestroy(s2);
}

// round 17
// speedup vs baseline: 1.0696x; 1.0696x over previous
#include <cuda_runtime.h>
#include <cstdint>
#include <math.h>

#define MAXN 50000
#define MAXE 800000
#define DIM  128

typedef unsigned long long ull;
#define FULLMASK 0xffffffffu

// ---- scratch (static __device__ arrays; no allocation allowed) ----
// counts/cursor are zero at module load; the zero_kernel on the side stream
// restores them each call (ordered before the join), so every invocation and
// every graph replay starts from zeros.
__device__ float  g_q   [MAXN * DIM];
__device__ float  g_k   [MAXN * DIM];
__device__ float  g_v   [MAXN * DIM];
__device__ float  g_skip[MAXN * DIM];
__device__ float  g_qwe [MAXN * 2 * DIM];   // [N][h*128+d]
__device__ float  g_z   [MAXN * 2 * DIM];   // [N][h*128+d]
__device__ float  g_vagg[MAXN * DIM];
__device__ float  g_pre [MAXN * DIM];
__device__ float  g_Wqe [2 * DIM * DIM];    // [h][k][d]
__device__ float  g_bqe [2 * DIM];          // [h][d]
__device__ int    g_counts [MAXN];
__device__ int    g_cursor [MAXN];
__device__ int    g_offsets[MAXN + 1];
__device__ int    g_perm   [MAXE];

// ------------------------------------------------------------------
__device__ __forceinline__ void ffma2(ull &d, ull a, ull b) {
    asm("fma.rn.f32x2 %0, %1, %2, %0;" : "+l"(d) : "l"(a), "l"(b));
}
__device__ __forceinline__ float lo32(ull v) { union { ull u; float2 f; } c; c.u = v; return c.f.x; }
__device__ __forceinline__ float hi32(ull v) { union { ull u; float2 f; } c; c.u = v; return c.f.y; }

// ------------------------------------------------------------------
__global__ void zero_kernel(int* a, int* b, int n) {
    int i = blockIdx.x * blockDim.x + threadIdx.x;
    if (i < n) { a[i] = 0; b[i] = 0; }
}

__global__ void count_kernel(const int* __restrict__ dst, int* __restrict__ counts, int e) {
    int i = blockIdx.x * blockDim.x + threadIdx.x;
    if (i < e) atomicAdd(&counts[dst[i]], 1);
}

// Wqe[h][k][d] = sum_c Wq[k][h*64+c] * We[d][h*64+c] ; bqe likewise
__global__ void wqe_prep(const float* __restrict__ Wq, const float* __restrict__ bq,
                         const float* __restrict__ We,
                         float* __restrict__ Wqe, float* __restrict__ bqe) {
    __shared__ float wq_s[16][64];
    const int h  = blockIdx.x >> 3;
    const int kt = (blockIdx.x & 7) * 16;
    const int d  = threadIdx.x;

    for (int idx = d; idx < 16 * 64; idx += 128) {
        int kk = idx >> 6, c = idx & 63;
        wq_s[kk][c] = Wq[(size_t)(kt + kk) * DIM + h * 64 + c];
    }
    __syncthreads();

    float wer[64];
#pragma unroll
    for (int c4 = 0; c4 < 64; c4 += 4) {
        float4 w = *(const float4*)&We[(size_t)d * DIM + h * 64 + c4];
        wer[c4 + 0] = w.x; wer[c4 + 1] = w.y; wer[c4 + 2] = w.z; wer[c4 + 3] = w.w;
    }
#pragma unroll 4
    for (int kk = 0; kk < 16; kk++) {
        float acc = 0.f;
#pragma unroll
        for (int c = 0; c < 64; c++) acc += wq_s[kk][c] * wer[c];
        Wqe[(size_t)h * DIM * DIM + (size_t)(kt + kk) * DIM + d] = acc;
    }
    if (kt == 0) {
        float acc = 0.f;
#pragma unroll
        for (int c = 0; c < 64; c++) acc += bq[h * 64 + c] * wer[c];
        bqe[h * DIM + d] = acc;
    }
}

// single-block scan over n counts -> exclusive offsets, offsets[n] = total
__global__ void scan_kernel(const int* __restrict__ counts, int* __restrict__ offsets, int n) {
    __shared__ int part[1024];
    int tid = threadIdx.x;
    int ch = (n + 1023) >> 10;
    int b = tid * ch;
    int eidx = b + ch; if (eidx > n) eidx = n;
    int s = 0;
    for (int i = b; i < eidx; i++) s += counts[i];
    part[tid] = s;
    __syncthreads();
    for (int off = 1; off < 1024; off <<= 1) {
        int v = (tid >= off) ? part[tid - off] : 0;
        __syncthreads();
        part[tid] += v;
        __syncthreads();
    }
    int excl = (tid == 0) ? 0 : part[tid - 1];
    for (int i = b; i < eidx; i++) { offsets[i] = excl; excl += counts[i]; }
    if (tid == 1023) offsets[n] = part[1023];
}

__global__ void scatter_kernel(const int* __restrict__ dst, const int* __restrict__ offsets,
                               int* __restrict__ cursor, int* __restrict__ perm, int e) {
    int i = blockIdx.x * blockDim.x + threadIdx.x;
    if (i < e) {
        int d = dst[i];
        int pos = offsets[d] + atomicAdd(&cursor[d], 1);
        perm[pos] = i;
    }
}

// ------------------------------------------------------------------
// Fused x-GEMM (round-14 winner, unchanged).
struct Slice { const float* B; const float* bias; float* C; int ldC; int cOff; };
struct Slices6 { Slice s[6]; };

#define GSTR 10   // padded group stride in float2 (8 data + 2 pad)

__global__ __launch_bounds__(128, 3)
void gemm_multi(const float* __restrict__ A, int M, Slices6 sl) {
    constexpr int N = 128, CPT = 8, ROWG = 8, RPT = 8, PAIRS = 4;
    constexpr int KC = 16, STR = 12;
    constexpr int XSW = (64 / RPT) * STR;      // 96
    constexpr int WSW = (N / 8) * GSTR;        // 160 float2 per k row

    __shared__ float  xs [2][KC][XSW];
    __shared__ float2 ws2[2][KC][WSW];

    const Slice s = sl.s[blockIdx.y];
    const int tid = threadIdx.x;
    const int y = tid % ROWG;
    const int x = tid / ROWG;
    const int n0 = blockIdx.x * 64;
    const int abase = y * STR;
    const int wbase = x * GSTR;

    ull acc[PAIRS][CPT];
#pragma unroll
    for (int p = 0; p < PAIRS; p++)
#pragma unroll
        for (int c = 0; c < CPT; c++) acc[p][c] = 0ull;

    auto stage = [&](int bb, int kc) {
        int rr = tid >> 1;
        int kh = (tid & 1) * 8;
        int row = n0 + rr;
        float4 a0 = make_float4(0.f, 0.f, 0.f, 0.f), a1 = a0;
        if (row < M) {
            const float* ap = &A[(size_t)row * DIM + kc + kh];
            a0 = *(const float4*)ap;
            a1 = *(const float4*)(ap + 4);
        }
        int pp = (rr / RPT) * STR + (rr % RPT);
        xs[bb][kh + 0][pp] = a0.x; xs[bb][kh + 1][pp] = a0.y;
        xs[bb][kh + 2][pp] = a0.z; xs[bb][kh + 3][pp] = a0.w;
        xs[bb][kh + 4][pp] = a1.x; xs[bb][kh + 5][pp] = a1.y;
        xs[bb][kh + 6][pp] = a1.z; xs[bb][kh + 7][pp] = a1.w;
#pragma unroll
        for (int it = 0; it < KC * N / (128 * 4); it++) {
            int idx = tid + it * 128;
            int kk = idx / (N / 4);
            int j  = (idx * 4) % N;
            int jp = (j >> 3) * GSTR + (j & 7);
            float4 w = *(const float4*)&s.B[(size_t)(kc + kk) * DIM + j];
            ws2[bb][kk][jp + 0] = make_float2(w.x, w.x);
            ws2[bb][kk][jp + 1] = make_float2(w.y, w.y);
            ws2[bb][kk][jp + 2] = make_float2(w.z, w.z);
            ws2[bb][kk][jp + 3] = make_float2(w.w, w.w);
        }
    };

    stage(0, 0);
    __syncthreads();
    const int nIt = DIM / KC;
    for (int ch = 0; ch < nIt; ch++) {
        int cur = ch & 1;
        if (ch + 1 < nIt) stage(cur ^ 1, (ch + 1) * KC);
#pragma unroll
        for (int k = 0; k < KC; k++) {
            ulonglong2 a0 = *(const ulonglong2*)&xs[cur][k][abase];
            ulonglong2 a1 = *(const ulonglong2*)&xs[cur][k][abase + 4];
            ull ap[PAIRS] = { a0.x, a0.y, a1.x, a1.y };
            ulonglong2 wq0 = *(const ulonglong2*)&ws2[cur][k][wbase + 0];
            ulonglong2 wq1 = *(const ulonglong2*)&ws2[cur][k][wbase + 2];
            ulonglong2 wq2 = *(const ulonglong2*)&ws2[cur][k][wbase + 4];
            ulonglong2 wq3 = *(const ulonglong2*)&ws2[cur][k][wbase + 6];
            ull wd[CPT] = { wq0.x, wq0.y, wq1.x, wq1.y, wq2.x, wq2.y, wq3.x, wq3.y };
#pragma unroll
            for (int p = 0; p < PAIRS; p++)
#pragma unroll
                for (int c = 0; c < CPT; c++)
                    ffma2(acc[p][c], ap[p], wd[c]);
        }
        __syncthreads();
    }

    float bj[CPT];
#pragma unroll
    for (int c = 0; c < CPT; c++) bj[c] = s.bias[s.cOff + CPT * x + c];
#pragma unroll
    for (int p = 0; p < PAIRS; p++) {
#pragma unroll
        for (int half = 0; half < 2; half++) {
            int row = n0 + RPT * y + 2 * p + half;
            if (row >= M) continue;
            float* cp = &s.C[(size_t)row * s.ldC + s.cOff + CPT * x];
            float4 o0, o1;
            if (half == 0) {
                o0 = make_float4(lo32(acc[p][0]) + bj[0], lo32(acc[p][1]) + bj[1],
                                 lo32(acc[p][2]) + bj[2], lo32(acc[p][3]) + bj[3]);
                o1 = make_float4(lo32(acc[p][4]) + bj[4], lo32(acc[p][5]) + bj[5],
                                 lo32(acc[p][6]) + bj[6], lo32(acc[p][7]) + bj[7]);
            } else {
                o0 = make_float4(hi32(acc[p][0]) + bj[0], hi32(acc[p][1]) + bj[1],
                                 hi32(acc[p][2]) + bj[2], hi32(acc[p][3]) + bj[3]);
                o1 = make_float4(hi32(acc[p][4]) + bj[4], hi32(acc[p][5]) + bj[5],
                                 hi32(acc[p][6]) + bj[6], hi32(acc[p][7]) + bj[7]);
            }
            *(float4*)cp       = o0;
            *(float4*)(cp + 4) = o1;
        }
    }
}

// ------------------------------------------------------------------
// Fused pre kernel: grid.y = head h. 64 rows x 64 cols per block, 128 threads.
// pre[:, h*64:(h+1)*64] = z[:, h*128:(h+1)*128] @ We[:, h*64:(h+1)*64] + vagg + skip
__global__ __launch_bounds__(128, 3)
void gemm_pre(const float* __restrict__ z, const float* __restrict__ We,
              const float* __restrict__ vagg, const float* __restrict__ skp,
              float* __restrict__ pre, int M) {
    constexpr int N = 64, CPT = 8;
    constexpr int COLG = N / CPT;      // 8
    constexpr int ROWG = 128 / COLG;   // 16
    constexpr int RPT  = 64 / ROWG;    // 4
    constexpr int PAIRS = RPT / 2;     // 2
    constexpr int KC = 16, STR = 12;
    constexpr int XSW = (64 / RPT) * STR;
    constexpr int WSW = (N / 8) * GSTR;

    __shared__ float  xs [2][KC][XSW];
    __shared__ float2 ws2[2][KC][WSW];

    const int h = blockIdx.y;
    const int aOff = h * 128;
    const int cOff = h * 64;
    const float* B = We + h * 64;

    const int tid = threadIdx.x;
    const int y = tid % ROWG;
    const int x = tid / ROWG;
    const int n0 = blockIdx.x * 64;
    const int abase = y * STR;
    const int wbase = x * GSTR;

    ull acc[PAIRS][CPT];
#pragma unroll
    for (int p = 0; p < PAIRS; p++)
#pragma unroll
        for (int c = 0; c < CPT; c++) acc[p][c] = 0ull;

    auto stage = [&](int bb, int kc) {
        int rr = tid >> 1;
        int kh = (tid & 1) * 8;
        int row = n0 + rr;
        float4 a0 = make_float4(0.f, 0.f, 0.f, 0.f), a1 = a0;
        if (row < M) {
            const float* ap = &z[(size_t)row * 256 + aOff + kc + kh];
            a0 = *(const float4*)ap;
            a1 = *(const float4*)(ap + 4);
        }
        int pp = (rr / RPT) * STR + (rr % RPT);
        xs[bb][kh + 0][pp] = a0.x; xs[bb][kh + 1][pp] = a0.y;
        xs[bb][kh + 2][pp] = a0.z; xs[bb][kh + 3][pp] = a0.w;
        xs[bb][kh + 4][pp] = a1.x; xs[bb][kh + 5][pp] = a1.y;
        xs[bb][kh + 6][pp] = a1.z; xs[bb][kh + 7][pp] = a1.w;
#pragma unroll
        for (int it = 0; it < KC * N / (128 * 4); it++) {   // 2 its
            int idx = tid + it * 128;
            int kk = idx / (N / 4);
            int j  = (idx * 4) % N;
            int jp = (j >> 3) * GSTR + (j & 7);
            float4 w = *(const float4*)&B[(size_t)(kc + kk) * DIM + j];
            ws2[bb][kk][jp + 0] = make_float2(w.x, w.x);
            ws2[bb][kk][jp + 1] = make_float2(w.y, w.y);
            ws2[bb][kk][jp + 2] = make_float2(w.z, w.z);
            ws2[bb][kk][jp + 3] = make_float2(w.w, w.w);
        }
    };

    stage(0, 0);
    __syncthreads();
    const int nIt = DIM / KC;                 // K = 128
    for (int ch = 0; ch < nIt; ch++) {
        int cur = ch & 1;
        if (ch + 1 < nIt) stage(cur ^ 1, (ch + 1) * KC);
#pragma unroll
        for (int k = 0; k < KC; k++) {
            ulonglong2 a0 = *(const ulonglong2*)&xs[cur][k][abase];
            ull ap[PAIRS] = { a0.x, a0.y };
            ulonglong2 wq0 = *(const ulonglong2*)&ws2[cur][k][wbase + 0];
            ulonglong2 wq1 = *(const ulonglong2*)&ws2[cur][k][wbase + 2];
            ulonglong2 wq2 = *(const ulonglong2*)&ws2[cur][k][wbase + 4];
            ulonglong2 wq3 = *(const ulonglong2*)&ws2[cur][k][wbase + 6];
            ull wd[CPT] = { wq0.x, wq0.y, wq1.x, wq1.y, wq2.x, wq2.y, wq3.x, wq3.y };
#pragma unroll
            for (int p = 0; p < PAIRS; p++)
#pragma unroll
                for (int c = 0; c < CPT; c++)
                    ffma2(acc[p][c], ap[p], wd[c]);
        }
        __syncthreads();
    }

#pragma unroll
    for (int p = 0; p < PAIRS; p++) {
#pragma unroll
        for (int half = 0; half < 2; half++) {
            int row = n0 + RPT * y + 2 * p + half;
            if (row >= M) continue;
            float o[CPT];
#pragma unroll
            for (int c = 0; c < CPT; c++)
                o[c] = half ? hi32(acc[p][c]) : lo32(acc[p][c]);
            size_t abidx = (size_t)row * DIM + cOff + CPT * x;
            float4 a = *(const float4*)&vagg[abidx];
            float4 b = *(const float4*)&vagg[abidx + 4];
            o[0] += a.x; o[1] += a.y; o[2] += a.z; o[3] += a.w;
            o[4] += b.x; o[5] += b.y; o[6] += b.z; o[7] += b.w;
            float4 c0 = *(const float4*)&skp[abidx];
            float4 c1 = *(const float4*)&skp[abidx + 4];
            o[0] += c0.x; o[1] += c0.y; o[2] += c0.z; o[3] += c0.w;
            o[4] += c1.x; o[5] += c1.y; o[6] += c1.z; o[7] += c1.w;
            float* cp = &pre[abidx];
            *(float4*)cp       = make_float4(o[0], o[1], o[2], o[3]);
            *(float4*)(cp + 4) = make_float4(o[4], o[5], o[6], o[7]);
        }
    }
}

// ------------------------------------------------------------------
// Generic double-buffered FFMA2 GEMM (proj), unchanged from round 14.
template<int N>
__global__ __launch_bounds__(128, 3)
void gemm_p(const float* __restrict__ A, int ldA, int aOff,
            const float* __restrict__ B, int ldB,
            int K,
            const float* __restrict__ bias,
            const float* __restrict__ add0, const float* __restrict__ add1, int ldAdd,
            float* __restrict__ C, int ldC, int cOff, int M) {
    constexpr int CPT   = 8;
    constexpr int COLG  = N / CPT;
    constexpr int ROWG  = 128 / COLG;
    constexpr int RPT   = 64 / ROWG;
    constexpr int PAIRS = RPT / 2;
    constexpr int KC    = 16;
    constexpr int STR   = 12;
    constexpr int XSW   = (64 / RPT) * STR;
    constexpr int WSW   = (N / 8) * GSTR;

    __shared__ float  xs [2][KC][XSW];
    __shared__ float2 ws2[2][KC][WSW];

    const int tid = threadIdx.x;
    const int y = tid % ROWG;
    const int x = tid / ROWG;
    const int n0 = blockIdx.x * 64;
    const int abase = y * STR;
    const int wbase = x * GSTR;

    ull acc[PAIRS][CPT];
#pragma unroll
    for (int p = 0; p < PAIRS; p++)
#pragma unroll
        for (int c = 0; c < CPT; c++) acc[p][c] = 0ull;

    auto stage = [&](int bb, int kc) {
        int rr = tid >> 1;
        int kh = (tid & 1) * 8;
        int row = n0 + rr;
        float4 a0 = make_float4(0.f, 0.f, 0.f, 0.f), a1 = a0;
        if (row < M) {
            const float* ap = &A[(size_t)row * ldA + aOff + kc + kh];
            a0 = *(const float4*)ap;
            a1 = *(const float4*)(ap + 4);
        }
        int pp = (rr / RPT) * STR + (rr % RPT);
        xs[bb][kh + 0][pp] = a0.x; xs[bb][kh + 1][pp] = a0.y;
        xs[bb][kh + 2][pp] = a0.z; xs[bb][kh + 3][pp] = a0.w;
        xs[bb][kh + 4][pp] = a1.x; xs[bb][kh + 5][pp] = a1.y;
        xs[bb][kh + 6][pp] = a1.z; xs[bb][kh + 7][pp] = a1.w;
#pragma unroll
        for (int it = 0; it < KC * N / (128 * 4); it++) {
            int idx = tid + it * 128;
            int kk = idx / (N / 4);
            int j  = (idx * 4) % N;
            int jp = (j >> 3) * GSTR + (j & 7);
            float4 w = *(const float4*)&B[(size_t)(kc + kk) * ldB + j];
            ws2[bb][kk][jp + 0] = make_float2(w.x, w.x);
            ws2[bb][kk][jp + 1] = make_float2(w.y, w.y);
            ws2[bb][kk][jp + 2] = make_float2(w.z, w.z);
            ws2[bb][kk][jp + 3] = make_float2(w.w, w.w);
        }
    };

    stage(0, 0);
    __syncthreads();
    const int nIt = K / KC;
    for (int ch = 0; ch < nIt; ch++) {
        int cur = ch & 1;
        if (ch + 1 < nIt) stage(cur ^ 1, (ch + 1) * KC);
#pragma unroll
        for (int k = 0; k < KC; k++) {
            ull ap[PAIRS];
            if (PAIRS == 4) {
                ulonglong2 a0 = *(const ulonglong2*)&xs[cur][k][abase];
                ulonglong2 a1 = *(const ulonglong2*)&xs[cur][k][abase + 4];
                ap[0] = a0.x; ap[1] = a0.y;
                ap[PAIRS - 2] = a1.x; ap[PAIRS - 1] = a1.y;
            } else {
                ulonglong2 a0 = *(const ulonglong2*)&xs[cur][k][abase];
                ap[0] = a0.x; ap[PAIRS - 1] = a0.y;
            }
            ulonglong2 wq0 = *(const ulonglong2*)&ws2[cur][k][wbase + 0];
            ulonglong2 wq1 = *(const ulonglong2*)&ws2[cur][k][wbase + 2];
            ulonglong2 wq2 = *(const ulonglong2*)&ws2[cur][k][wbase + 4];
            ulonglong2 wq3 = *(const ulonglong2*)&ws2[cur][k][wbase + 6];
            ull wd[CPT] = { wq0.x, wq0.y, wq1.x, wq1.y, wq2.x, wq2.y, wq3.x, wq3.y };
#pragma unroll
            for (int p = 0; p < PAIRS; p++)
#pragma unroll
                for (int c = 0; c < CPT; c++)
                    ffma2(acc[p][c], ap[p], wd[c]);
        }
        __syncthreads();
    }

    float bj[CPT];
#pragma unroll
    for (int c = 0; c < CPT; c++) bj[c] = bias ? bias[cOff + CPT * x + c] : 0.f;
#pragma unroll
    for (int p = 0; p < PAIRS; p++) {
#pragma unroll
        for (int half = 0; half < 2; half++) {
            int row = n0 + RPT * y + 2 * p + half;
            if (row >= M) continue;
            float o[CPT];
#pragma unroll
            for (int c = 0; c < CPT; c++)
                o[c] = (half ? hi32(acc[p][c]) : lo32(acc[p][c])) + bj[c];
            size_t abidx = (size_t)row * ldAdd + cOff + CPT * x;
            if (add0) {
                float4 a = *(const float4*)&add0[abidx];
                float4 b = *(const float4*)&add0[abidx + 4];
                o[0] += a.x; o[1] += a.y; o[2] += a.z; o[3] += a.w;
                o[4] += b.x; o[5] += b.y; o[6] += b.z; o[7] += b.w;
            }
            if (add1) {
                float4 a = *(const float4*)&add1[abidx];
                float4 b = *(const float4*)&add1[abidx + 4];
                o[0] += a.x; o[1] += a.y; o[2] += a.z; o[3] += a.w;
                o[4] += b.x; o[5] += b.y; o[6] += b.z; o[7] += b.w;
            }
            float* cp = &C[(size_t)row * ldC + cOff + CPT * x];
            *(float4*)cp       = make_float4(o[0], o[1], o[2], o[3]);
            *(float4*)(cp + 4) = make_float4(o[4], o[5], o[6], o[7]);
        }
    }
}

// ------------------------------------------------------------------
// Single-pass attention (round-14 winner, reverted verbatim).
__global__ void attn_kernel(const int* __restrict__ src_arr, const int* __restrict__ offsets,
                            const int* __restrict__ perm,
                            const float* __restrict__ q, const float* __restrict__ k,
                            const float* __restrict__ v, const float* __restrict__ qwe,
                            const float* __restrict__ edge_attr,
                            float* __restrict__ z, float* __restrict__ vagg, int n) {
    int warp = (blockIdx.x * blockDim.x + threadIdx.x) >> 5;
    int lane = threadIdx.x & 31;
    if (warp >= n) return;
    const int i = warp;
    const int beg = offsets[i], end = offsets[i + 1];
    const int head = lane >> 4;

    float4 q4 = *(const float4*)&q  [(size_t)i * 128 + lane * 4];
    float4 w0 = *(const float4*)&qwe[(size_t)i * 256 + lane * 4];
    float4 w1 = *(const float4*)&qwe[(size_t)i * 256 + 128 + lane * 4];

    float l0 = 0.f, l1 = 0.f;
    float4 az0 = make_float4(0.f, 0.f, 0.f, 0.f);
    float4 az1 = az0;
    float4 av  = az0;

    for (int c = beg; c < end; c += 32) {
        int t = c + lane;
        int epre = 0, spre = 0;
        if (t < end) { epre = perm[t]; spre = src_arr[epre]; }
        int cnt = end - c; if (cnt > 32) cnt = 32;

        int ej = __shfl_sync(FULLMASK, epre, 0);
        int sj = __shfl_sync(FULLMASK, spre, 0);
        float4 ea = __ldcs((const float4*)&edge_attr[(size_t)ej * 128 + lane * 4]);
        float4 k4 = *(const float4*)&k[(size_t)sj * 128 + lane * 4];
        float4 v4 = *(const float4*)&v[(size_t)sj * 128 + lane * 4];

        for (int j = 0; j < cnt; j++) {
            float4 ean = ea, k4n = k4, v4n = v4;
            if (j + 1 < cnt) {
                int ej1 = __shfl_sync(FULLMASK, epre, j + 1);
                int sj1 = __shfl_sync(FULLMASK, spre, j + 1);
                ean = __ldcs((const float4*)&edge_attr[(size_t)ej1 * 128 + lane * 4]);
                k4n = *(const float4*)&k[(size_t)sj1 * 128 + lane * 4];
                v4n = *(const float4*)&v[(size_t)sj1 * 128 + lane * 4];
            }

            float pqk = q4.x * k4.x + q4.y * k4.y + q4.z * k4.z + q4.w * k4.w;
            float s0  = ea.x * w0.x + ea.y * w0.y + ea.z * w0.z + ea.w * w0.w;
            float s1  = ea.x * w1.x + ea.y * w1.y + ea.z * w1.z + ea.w * w1.w;
            if (head) s1 += pqk; else s0 += pqk;

#pragma unroll
            for (int off = 16; off; off >>= 1) {
                s0 += __shfl_xor_sync(FULLMASK, s0, off);
                s1 += __shfl_xor_sync(FULLMASK, s1, off);
            }

            float e0 = __expf(fminf(s0 * 0.125f, 80.f));
            float e1 = __expf(fminf(s1 * 0.125f, 80.f));
            l0 += e0; l1 += e1;
            az0.x += e0 * ea.x; az0.y += e0 * ea.y;
            az0.z += e0 * ea.z; az0.w += e0 * ea.w;
            az1.x += e1 * ea.x; az1.y += e1 * ea.y;
            az1.z += e1 * ea.z; az1.w += e1 * ea.w;
            float eh = head ? e1 : e0;
            av.x += eh * v4.x; av.y += eh * v4.y;
            av.z += eh * v4.z; av.w += eh * v4.w;

            ea = ean; k4 = k4n; v4 = v4n;
        }
    }

    float il0 = (end > beg) ? 1.f / l0 : 0.f;
    float il1 = (end > beg) ? 1.f / l1 : 0.f;
    float4 o0 = make_float4(az0.x * il0, az0.y * il0, az0.z * il0, az0.w * il0);
    float4 o1 = make_float4(az1.x * il1, az1.y * il1, az1.z * il1, az1.w * il1);
    *(float4*)&z[(size_t)i * 256 + lane * 4]       = o0;
    *(float4*)&z[(size_t)i * 256 + 128 + lane * 4] = o1;
    float ilh = head ? il1 : il0;
    float4 ov = make_float4(av.x * ilh, av.y * ilh, av.z * ilh, av.w * ilh);
    *(float4*)&vagg[(size_t)i * 128 + lane * 4] = ov;
}

// ------------------------------------------------------------------
extern "C" void kernel_launch(void* const* d_in, const int* in_sizes, int n_in,
                              void* d_out, int out_size) {
    const float* x     = (const float*)d_in[0];
    const float* eattr = (const float*)d_in[1];
    const float* Wq    = (const float*)d_in[2];
    const float* bq    = (const float*)d_in[3];
    const float* Wk    = (const float*)d_in[4];
    const float* bk    = (const float*)d_in[5];
    const float* Wv    = (const float*)d_in[6];
    const float* bv    = (const float*)d_in[7];
    const float* We    = (const float*)d_in[8];
    const float* Wskip = (const float*)d_in[9];
    const float* bskip = (const float*)d_in[10];
    const float* Wproj = (const float*)d_in[11];
    const float* bproj = (const float*)d_in[12];
    const int*   ei    = (const int*)d_in[13];

    const int n = in_sizes[0] / DIM;       // 50000
    const int e = in_sizes[1] / DIM;       // 800000
    const int* src = ei;                   // edge_index[0]
    const int* dst = ei + e;               // edge_index[1]

    float *pq, *pk, *pv, *pskip, *pqwe, *pz, *pvagg, *ppre, *pWqe, *pbqe;
    int *pcnt, *pcur, *poff, *pperm;
    cudaGetSymbolAddress((void**)&pq,    g_q);
    cudaGetSymbolAddress((void**)&pk,    g_k);
    cudaGetSymbolAddress((void**)&pv,    g_v);
    cudaGetSymbolAddress((void**)&pskip, g_skip);
    cudaGetSymbolAddress((void**)&pqwe,  g_qwe);
    cudaGetSymbolAddress((void**)&pz,    g_z);
    cudaGetSymbolAddress((void**)&pvagg, g_vagg);
    cudaGetSymbolAddress((void**)&ppre,  g_pre);
    cudaGetSymbolAddress((void**)&pWqe,  g_Wqe);
    cudaGetSymbolAddress((void**)&pbqe,  g_bqe);
    cudaGetSymbolAddress((void**)&pcnt,  g_counts);
    cudaGetSymbolAddress((void**)&pcur,  g_cursor);
    cudaGetSymbolAddress((void**)&poff,  g_offsets);
    cudaGetSymbolAddress((void**)&pperm, g_perm);

    const int gb = (n + 63) / 64;          // 64-row GEMM blocks (782)
    const int wb = (n * 32 + 255) / 256;   // warp-per-node grid
    const int cb = (e + 255) / 256;        // edge-parallel blocks

    // ---- side stream for CSR build + skip GEMM (joined via events) ----
    cudaStream_t s2;
    cudaStreamCreateWithFlags(&s2, cudaStreamNonBlocking);
    cudaEvent_t evFork, evCsr, evSkip;
    cudaEventCreateWithFlags(&evFork, cudaEventDisableTiming);
    cudaEventCreateWithFlags(&evCsr,  cudaEventDisableTiming);
    cudaEventCreateWithFlags(&evSkip, cudaEventDisableTiming);

    // fork
    cudaEventRecord(evFork, 0);
    cudaStreamWaitEvent(s2, evFork, 0);

    // main: Wqe precompute (needed by gemm_multi slices 4,5)
    wqe_prep<<<16, 128>>>(Wq, bq, We, pWqe, pbqe);

    // s2: CSR chain (counts/cursor are zero on entry; re-zeroed below)
    count_kernel<<<cb, 256, 0, s2>>>(dst, pcnt, e);
    scan_kernel<<<1, 1024, 0, s2>>>(pcnt, poff, n);

    // main: 5-slice fused x-GEMM (q, k, v, qwe0, qwe1) -- overlaps CSR chain
    Slices6 sl;
    sl.s[0] = { Wq,              bq,    pq,    DIM, 0   };
    sl.s[1] = { Wk,              bk,    pk,    DIM, 0   };
    sl.s[2] = { Wv,              bv,    pv,    DIM, 0   };
    sl.s[3] = { pWqe,            pbqe,  pqwe,  256, 0   };
    sl.s[4] = { pWqe + DIM*DIM,  pbqe,  pqwe,  256, 128 };
    gemm_multi<<<dim3(gb, 5), 128>>>(x, n, sl);

    // s2: finish CSR, restore counts/cursor for next replay, then skip GEMM
    scatter_kernel<<<cb, 256, 0, s2>>>(dst, poff, pcur, pperm, e);
    zero_kernel<<<(n + 255) / 256, 256, 0, s2>>>(pcnt, pcur, n);
    cudaEventRecord(evCsr, s2);
    Slices6 sk;
    sk.s[0] = { Wskip, bskip, pskip, DIM, 0 };
    gemm_multi<<<dim3(gb, 1), 128, 0, s2>>>(x, n, sk);   // overlaps attn
    cudaEventRecord(evSkip, s2);

    // main: attention needs q/k/v/qwe (main) + CSR (evCsr)
    cudaStreamWaitEvent(0, evCsr, 0);
    attn_kernel<<<wb, 256>>>(src, poff, pperm, pq, pk, pv, pqwe, eattr, pz, pvagg, n);

    // main: pre needs vagg/z (attn) + skip (evSkip) -- both heads in ONE launch
    cudaStreamWaitEvent(0, evSkip, 0);
    gemm_pre<<<dim3(gb, 2), 128>>>(pz, We, pvagg, pskip, ppre, n);

    // main: out = pre @ Wproj + bproj
    gemm_p<128><<<gb, 128>>>(ppre, DIM, 0, Wproj, DIM, DIM, bproj, nullptr, nullptr, 0, (float*)d_out, DIM, 0, n);

    cudaEventDestroy(evFork);
    cudaEventDestroy(evCsr);
    cudaEventDestroy(evSkip);
    cudaStreamDestroy(s2);
}